// round 1
// baseline (speedup 1.0000x reference)
#include <cuda_runtime.h>
#include <cuda_bf16.h>

#define NN 65536
#define KK 6
#define MM 688
#define MQ (MM / 4)   // 172 float4 per (n,k) row

__global__ __launch_bounds__(256)
void mlp_msg_agg_kernel(
    const float4* __restrict__ msgs,   // [N, K, MQ] as float4
    const int*    __restrict__ counts, // [N]
    const float*  __restrict__ ts,     // [N]
    const float*  __restrict__ W1,     // [6,3] row-major
    const float*  __restrict__ b1,     // [3]
    const float*  __restrict__ W2,     // [3,2]
    const float*  __restrict__ b2,     // [2]
    const float*  __restrict__ W3,     // [2,1]
    const float*  __restrict__ b3,     // [1]
    float4*       __restrict__ out,    // [N, MQ] as float4
    float*        __restrict__ out_ts, // [N] or null
    int write_ts)
{
    const int idx = blockIdx.x * blockDim.x + threadIdx.x;

    // piggyback the timestamps passthrough on the first N threads
    if (write_ts && idx < NN) {
        out_ts[idx] = ts[idx];
    }

    if (idx >= NN * MQ) return;

    const int n  = idx / MQ;
    const int mq = idx - n * MQ;

    int k0 = KK - counts[n];          // first valid slot
    if (k0 < 0) k0 = 0;
    if (k0 > KK) k0 = KK;

    // Weights into registers (L1-broadcast loads, tiny)
    float w1[KK * 3];
    #pragma unroll
    for (int i = 0; i < KK * 3; i++) w1[i] = W1[i];
    const float bb1_0 = b1[0], bb1_1 = b1[1], bb1_2 = b1[2];

    float w2[6];
    #pragma unroll
    for (int i = 0; i < 6; i++) w2[i] = W2[i];
    const float bb2_0 = b2[0], bb2_1 = b2[1];

    const float w3_0 = W3[0], w3_1 = W3[1];
    const float bb3  = b3[0];

    // h1 accumulators for the 4 lanes of the float4
    float h[4][3];
    #pragma unroll
    for (int l = 0; l < 4; l++) {
        h[l][0] = bb1_0; h[l][1] = bb1_1; h[l][2] = bb1_2;
    }

    const float4* base = msgs + (size_t)n * KK * MQ + mq;

    // Fully unrolled k-loop; k < k0 iterations become predicated-off LDGs
    // (no HBM transaction for zero-padded slots).
    #pragma unroll
    for (int k = 0; k < KK; k++) {
        if (k >= k0) {
            const float4 v = base[k * MQ];
            const float x0 = v.x, x1 = v.y, x2 = v.z, x3 = v.w;
            const float a = w1[k * 3 + 0];
            const float b = w1[k * 3 + 1];
            const float c = w1[k * 3 + 2];
            h[0][0] = fmaf(x0, a, h[0][0]); h[0][1] = fmaf(x0, b, h[0][1]); h[0][2] = fmaf(x0, c, h[0][2]);
            h[1][0] = fmaf(x1, a, h[1][0]); h[1][1] = fmaf(x1, b, h[1][1]); h[1][2] = fmaf(x1, c, h[1][2]);
            h[2][0] = fmaf(x2, a, h[2][0]); h[2][1] = fmaf(x2, b, h[2][1]); h[2][2] = fmaf(x2, c, h[2][2]);
            h[3][0] = fmaf(x3, a, h[3][0]); h[3][1] = fmaf(x3, b, h[3][1]); h[3][2] = fmaf(x3, c, h[3][2]);
        }
    }

    float res[4];
    #pragma unroll
    for (int l = 0; l < 4; l++) {
        const float a0 = fmaxf(h[l][0], 0.0f);
        const float a1 = fmaxf(h[l][1], 0.0f);
        const float a2 = fmaxf(h[l][2], 0.0f);
        // W2 is [3,2] row-major: W2[i*2 + j]
        float g0 = bb2_0;
        float g1 = bb2_1;
        g0 = fmaf(a0, w2[0], g0); g1 = fmaf(a0, w2[1], g1);
        g0 = fmaf(a1, w2[2], g0); g1 = fmaf(a1, w2[3], g1);
        g0 = fmaf(a2, w2[4], g0); g1 = fmaf(a2, w2[5], g1);
        g0 = fmaxf(g0, 0.0f);
        g1 = fmaxf(g1, 0.0f);
        res[l] = fmaf(g0, w3_0, fmaf(g1, w3_1, bb3));
    }

    float4 o;
    o.x = res[0]; o.y = res[1]; o.z = res[2]; o.w = res[3];
    out[idx] = o;
}

extern "C" void kernel_launch(void* const* d_in, const int* in_sizes, int n_in,
                              void* d_out, int out_size)
{
    const float4* msgs   = (const float4*)d_in[0];
    const int*    counts = (const int*)  d_in[1];
    const float*  ts     = (const float*)d_in[2];
    const float*  W1     = (const float*)d_in[3];
    const float*  b1     = (const float*)d_in[4];
    const float*  W2     = (const float*)d_in[5];
    const float*  b2     = (const float*)d_in[6];
    const float*  W3     = (const float*)d_in[7];
    const float*  b3     = (const float*)d_in[8];

    float* out = (float*)d_out;
    const int write_ts = (out_size >= NN * MM + NN) ? 1 : 0;
    float* out_ts = write_ts ? (out + (size_t)NN * MM) : nullptr;

    const int total = NN * MQ;                 // 11,272,192 threads
    const int threads = 256;
    const int blocks = (total + threads - 1) / threads;

    mlp_msg_agg_kernel<<<blocks, threads>>>(
        msgs, counts, ts, W1, b1, W2, b2, W3, b3,
        (float4*)out, out_ts, write_ts);
}

// round 2
// speedup vs baseline: 1.0385x; 1.0385x over previous
#include <cuda_runtime.h>
#include <cuda_bf16.h>

#define NN 65536
#define KK 6
#define MM 688
#define MQ (MM / 4)      // 172 float4 per (n,k) row
#define MH (MQ / 2)      // 86: each thread handles mq and mq+86

__global__ __launch_bounds__(256)
void mlp_msg_agg_kernel(
    const float4* __restrict__ msgs,   // [N, K, MQ] as float4
    const int*    __restrict__ counts, // [N]
    const float*  __restrict__ ts,     // [N]
    const float*  __restrict__ W1,     // [6,3] row-major
    const float*  __restrict__ b1,     // [3]
    const float*  __restrict__ W2,     // [3,2]
    const float*  __restrict__ b2,     // [2]
    const float*  __restrict__ W3,     // [2,1]
    const float*  __restrict__ b3,     // [1]
    float4*       __restrict__ out,    // [N, MQ] as float4
    float*        __restrict__ out_ts) // [N] or null
{
    const int idx = blockIdx.x * blockDim.x + threadIdx.x;

    // piggyback the timestamps passthrough on the first N threads
    if (out_ts != nullptr && idx < NN) {
        out_ts[idx] = __ldg(ts + idx);
    }

    if (idx >= NN * MH) return;

    const int n  = idx / MH;
    const int mq = idx - n * MH;      // 0..85; this thread also does mq+86

    int k0 = KK - __ldg(counts + n);  // first valid slot
    if (k0 < 0) k0 = 0;

    const float bb1_0 = __ldg(b1 + 0), bb1_1 = __ldg(b1 + 1), bb1_2 = __ldg(b1 + 2);

    // h1 accumulators: 2 float4s x 4 lanes x 3 hidden = 24 regs
    float h[8][3];
    #pragma unroll
    for (int l = 0; l < 8; l++) {
        h[l][0] = bb1_0; h[l][1] = bb1_1; h[l][2] = bb1_2;
    }

    const float4* base = msgs + (size_t)n * KK * MQ + mq;

    // Fully unrolled; invalid slots are predicated-off LDGs (no HBM traffic).
    #pragma unroll
    for (int k = 0; k < KK; k++) {
        if (k >= k0) {
            const float4 va = base[k * MQ];
            const float4 vb = base[k * MQ + MH];
            const float a = __ldg(W1 + k * 3 + 0);
            const float b = __ldg(W1 + k * 3 + 1);
            const float c = __ldg(W1 + k * 3 + 2);
            const float xa[4] = {va.x, va.y, va.z, va.w};
            const float xb[4] = {vb.x, vb.y, vb.z, vb.w};
            #pragma unroll
            for (int l = 0; l < 4; l++) {
                h[l][0]   = fmaf(xa[l], a, h[l][0]);
                h[l][1]   = fmaf(xa[l], b, h[l][1]);
                h[l][2]   = fmaf(xa[l], c, h[l][2]);
                h[l+4][0] = fmaf(xb[l], a, h[l+4][0]);
                h[l+4][1] = fmaf(xb[l], b, h[l+4][1]);
                h[l+4][2] = fmaf(xb[l], c, h[l+4][2]);
            }
        }
    }

    // Layers 2 & 3 (weights loaded late to shorten live ranges)
    const float w2_00 = __ldg(W2 + 0), w2_01 = __ldg(W2 + 1);
    const float w2_10 = __ldg(W2 + 2), w2_11 = __ldg(W2 + 3);
    const float w2_20 = __ldg(W2 + 4), w2_21 = __ldg(W2 + 5);
    const float bb2_0 = __ldg(b2 + 0), bb2_1 = __ldg(b2 + 1);
    const float w3_0  = __ldg(W3 + 0), w3_1  = __ldg(W3 + 1);
    const float bb3   = __ldg(b3 + 0);

    float res[8];
    #pragma unroll
    for (int l = 0; l < 8; l++) {
        const float a0 = fmaxf(h[l][0], 0.0f);
        const float a1 = fmaxf(h[l][1], 0.0f);
        const float a2 = fmaxf(h[l][2], 0.0f);
        float g0 = bb2_0, g1 = bb2_1;
        g0 = fmaf(a0, w2_00, g0); g1 = fmaf(a0, w2_01, g1);
        g0 = fmaf(a1, w2_10, g0); g1 = fmaf(a1, w2_11, g1);
        g0 = fmaf(a2, w2_20, g0); g1 = fmaf(a2, w2_21, g1);
        g0 = fmaxf(g0, 0.0f);
        g1 = fmaxf(g1, 0.0f);
        res[l] = fmaf(g0, w3_0, fmaf(g1, w3_1, bb3));
    }

    float4 oa, ob;
    oa.x = res[0]; oa.y = res[1]; oa.z = res[2]; oa.w = res[3];
    ob.x = res[4]; ob.y = res[5]; ob.z = res[6]; ob.w = res[7];
    float4* obase = out + (size_t)n * MQ + mq;
    obase[0]  = oa;
    obase[MH] = ob;
}

extern "C" void kernel_launch(void* const* d_in, const int* in_sizes, int n_in,
                              void* d_out, int out_size)
{
    const float4* msgs   = (const float4*)d_in[0];
    const int*    counts = (const int*)  d_in[1];
    const float*  ts     = (const float*)d_in[2];
    const float*  W1     = (const float*)d_in[3];
    const float*  b1     = (const float*)d_in[4];
    const float*  W2     = (const float*)d_in[5];
    const float*  b2     = (const float*)d_in[6];
    const float*  W3     = (const float*)d_in[7];
    const float*  b3     = (const float*)d_in[8];

    float* out = (float*)d_out;
    const int write_ts = (out_size >= NN * MM + NN) ? 1 : 0;
    float* out_ts = write_ts ? (out + (size_t)NN * MM) : nullptr;

    const int total = NN * MH;                 // 5,636,096 threads
    const int threads = 256;
    const int blocks = (total + threads - 1) / threads;

    mlp_msg_agg_kernel<<<blocks, threads>>>(
        msgs, counts, ts, W1, b1, W2, b2, W3, b3,
        (float4*)out, out_ts);
}